// round 6
// baseline (speedup 1.0000x reference)
#include <cuda_runtime.h>
#include <cuda_bf16.h>
#include <cstdint>
#include <math.h>

#define D      4096
#define E      512
#define BROWS  8192
#define NQ     (1ull*BROWS*D)
#define NENC   (1ull*BROWS*E)

#define OUT_Q_OFF    1ull
#define OUT_PERP_OFF (1ull + NQ)
#define OUT_ENC_OFF  (2ull + NQ)

#define MARGIN 4.0f

// ---------------- device scratch ----------------
__device__ float          g_cnorm[E];
__device__ float          g_dist[(size_t)BROWS * E];   // 16 MB approx distances
__device__ __nv_bfloat16  g_Cb[(size_t)E * D];         // 4 MB bf16 codebook
__device__ int            g_counts[E];
__device__ double         g_loss;

#define SWZ128(off) ((off) ^ (((off) >> 3) & 0x70))

__device__ __forceinline__ uint32_t smem_to_u32(const void* p) {
    uint32_t a;
    asm("{ .reg .u64 t; cvta.to.shared.u64 t, %1; cvt.u32.u64 %0, t; }" : "=r"(a) : "l"(p));
    return a;
}

// key packing: monotone float -> u32, argmin with ties -> lowest index
__device__ __forceinline__ unsigned long long make_key(float d, int idx) {
    unsigned int u = __float_as_uint(d);
    u = (u & 0x80000000u) ? ~u : (u | 0x80000000u);
    return ((unsigned long long)u << 32) | (unsigned int)idx;
}
__device__ __forceinline__ float key_to_float(unsigned long long k) {
    unsigned int u = (unsigned int)(k >> 32);
    u = (u & 0x80000000u) ? (u ^ 0x80000000u) : ~u;
    return __uint_as_float(u);
}

// ---------------- init ----------------
__global__ void init_kernel() {
    int i = blockIdx.x * blockDim.x + threadIdx.x;
    if (i < E)  g_counts[i] = 0;
    if (i == 0) g_loss = 0.0;
}

// ---------------- codebook: bf16 convert + exact norms (fused, 1 read) ----------------
__global__ __launch_bounds__(128)
void convCnorm_kernel(const float* __restrict__ C) {
    const int e = blockIdx.x;
    const float4* row = (const float4*)(C + (size_t)e * D);
    uint2* brow = (uint2*)(g_Cb + (size_t)e * D);
    float s = 0.f;
#pragma unroll
    for (int i = threadIdx.x; i < D / 4; i += 128) {
        float4 v = row[i];
        __nv_bfloat162 lo = __floats2bfloat162_rn(v.x, v.y);
        __nv_bfloat162 hi = __floats2bfloat162_rn(v.z, v.w);
        uint2 p; p.x = *(uint32_t*)&lo; p.y = *(uint32_t*)&hi;
        brow[i] = p;
        s += v.x * v.x + v.y * v.y + v.z * v.z + v.w * v.w;
    }
    for (int o = 16; o; o >>= 1) s += __shfl_down_sync(0xffffffffu, s, o);
    __shared__ float ws[4];
    if ((threadIdx.x & 31) == 0) ws[threadIdx.x >> 5] = s;
    __syncthreads();
    if (threadIdx.x == 0) g_cnorm[e] = ws[0] + ws[1] + ws[2] + ws[3];
}

// ---------------- mma.sync bf16 GEMM: approx distances ----------------
// CTA 256 thr = 8 warps (2M x 4N), tile M=64 x N=256, warp tile 32x64.
// K chunk = 64 bf16 (128B SW128 rows), double-buffered smem, 2 CTAs/SM.
#define TM 64
#define TN 256
#define CH 64
#define NCHUNK (D / CH)          // 64
#define A_BYTES 8192             // 64 rows * 128B
#define B_BYTES 32768            // 256 rows * 128B
#define GEMM_SMEM (2*A_BYTES + 2*B_BYTES)   // 81920

__global__ __launch_bounds__(256, 2)
void gemm_mma_kernel(const float* __restrict__ X) {
    extern __shared__ __align__(1024) char smem[];
    const int tid  = threadIdx.x;
    const int lane = tid & 31;
    const int wid  = tid >> 5;
    const int warpM = wid & 1;    // 0..1 (32-row bands)
    const int warpN = wid >> 1;   // 0..3 (64-col bands)
    const int rowBase = blockIdx.y * TM;
    const int colBase = blockIdx.x * TN;

    uint32_t sbA[2] = { smem_to_u32(smem),             smem_to_u32(smem) + A_BYTES };
    uint32_t sbB[2] = { smem_to_u32(smem) + 2*A_BYTES, smem_to_u32(smem) + 2*A_BYTES + B_BYTES };
    char* pA[2] = { smem, smem + A_BYTES };

    const float* Xg0 = X + (size_t)rowBase * D;
    const __nv_bfloat16* Cg0 = g_Cb + (size_t)colBase * D;

    // load coords: A 16 thr/row (float4), B 8 thr/row (16B)
    const int ar  = tid >> 4, ac4  = tid & 15;   // ar 0..15, row stride 16 (x4 -> 64 rows)
    const int br  = tid >> 3, bc16 = tid & 7;    // br 0..31, row stride 32 (x8 -> 256 rows)

    float acc[2][8][4];
#pragma unroll
    for (int mi = 0; mi < 2; mi++)
#pragma unroll
        for (int ni = 0; ni < 8; ni++)
#pragma unroll
            for (int r = 0; r < 4; r++) acc[mi][ni][r] = 0.f;

    float4 av[4];

    // ---- preload chunk 0 ----
#pragma unroll
    for (int i = 0; i < 8; i++) {
        int r = br + i * 32;
        uint32_t dst = sbB[0] + SWZ128((uint32_t)(r * 128 + bc16 * 16));
        const __nv_bfloat16* src = Cg0 + (size_t)r * D + bc16 * 8;
        asm volatile("cp.async.cg.shared.global [%0], [%1], 16;" :: "r"(dst), "l"(src));
    }
    asm volatile("cp.async.commit_group;" ::: "memory");
#pragma unroll
    for (int i = 0; i < 4; i++)
        av[i] = *(const float4*)(Xg0 + (size_t)(ar + i * 16) * D + ac4 * 4);

    const int a_r = lane & 15;
    const int a_c = (lane >> 4) * 16;
    const int b_n = ((lane >> 4) << 3) + (lane & 7);
    const int b_c = ((lane >> 3) & 1) * 16;

    for (int kt = 0; kt < NCHUNK; kt++) {
        const int buf = kt & 1;

        // STS A (convert fp32 -> bf16, SW128)
#pragma unroll
        for (int i = 0; i < 4; i++) {
            int r = ar + i * 16;
            __nv_bfloat162 lo = __floats2bfloat162_rn(av[i].x, av[i].y);
            __nv_bfloat162 hi = __floats2bfloat162_rn(av[i].z, av[i].w);
            uint2 p; p.x = *(uint32_t*)&lo; p.y = *(uint32_t*)&hi;
            *(uint2*)(pA[buf] + SWZ128((uint32_t)(r * 128 + ac4 * 8))) = p;
        }
        asm volatile("cp.async.wait_group 0;" ::: "memory");
        __syncthreads();

        // prefetch next chunk (overlaps MMA below)
        if (kt + 1 < NCHUNK) {
            const int nb = buf ^ 1;
            const int k0 = (kt + 1) * CH;
#pragma unroll
            for (int i = 0; i < 8; i++) {
                int r = br + i * 32;
                uint32_t dst = sbB[nb] + SWZ128((uint32_t)(r * 128 + bc16 * 16));
                const __nv_bfloat16* src = Cg0 + (size_t)r * D + k0 + bc16 * 8;
                asm volatile("cp.async.cg.shared.global [%0], [%1], 16;" :: "r"(dst), "l"(src));
            }
            asm volatile("cp.async.commit_group;" ::: "memory");
#pragma unroll
            for (int i = 0; i < 4; i++)
                av[i] = *(const float4*)(Xg0 + (size_t)(ar + i * 16) * D + k0 + ac4 * 4);
        }

        // ---- compute: 4 k16 steps ----
        const uint32_t aB = sbA[buf], bB = sbB[buf];
#pragma unroll
        for (int kk = 0; kk < 4; kk++) {
            uint32_t af[2][4], bfr[4][4];
#pragma unroll
            for (int mi = 0; mi < 2; mi++) {
                uint32_t addr = aB + SWZ128((uint32_t)((warpM * 32 + mi * 16 + a_r) * 128 + kk * 32 + a_c));
                asm volatile("ldmatrix.sync.aligned.m8n8.x4.shared.b16 {%0,%1,%2,%3}, [%4];"
                    : "=r"(af[mi][0]), "=r"(af[mi][1]), "=r"(af[mi][2]), "=r"(af[mi][3]) : "r"(addr));
            }
#pragma unroll
            for (int ng = 0; ng < 4; ng++) {
                uint32_t addr = bB + SWZ128((uint32_t)((warpN * 64 + ng * 16 + b_n) * 128 + kk * 32 + b_c));
                asm volatile("ldmatrix.sync.aligned.m8n8.x4.shared.b16 {%0,%1,%2,%3}, [%4];"
                    : "=r"(bfr[ng][0]), "=r"(bfr[ng][1]), "=r"(bfr[ng][2]), "=r"(bfr[ng][3]) : "r"(addr));
            }
#pragma unroll
            for (int mi = 0; mi < 2; mi++)
#pragma unroll
                for (int ng = 0; ng < 4; ng++) {
                    asm volatile("mma.sync.aligned.m16n8k16.row.col.f32.bf16.bf16.f32 "
                        "{%0,%1,%2,%3}, {%4,%5,%6,%7}, {%8,%9}, {%0,%1,%2,%3};"
                        : "+f"(acc[mi][2*ng][0]), "+f"(acc[mi][2*ng][1]),
                          "+f"(acc[mi][2*ng][2]), "+f"(acc[mi][2*ng][3])
                        : "r"(af[mi][0]), "r"(af[mi][1]), "r"(af[mi][2]), "r"(af[mi][3]),
                          "r"(bfr[ng][0]), "r"(bfr[ng][1]));
                    asm volatile("mma.sync.aligned.m16n8k16.row.col.f32.bf16.bf16.f32 "
                        "{%0,%1,%2,%3}, {%4,%5,%6,%7}, {%8,%9}, {%0,%1,%2,%3};"
                        : "+f"(acc[mi][2*ng+1][0]), "+f"(acc[mi][2*ng+1][1]),
                          "+f"(acc[mi][2*ng+1][2]), "+f"(acc[mi][2*ng+1][3])
                        : "r"(af[mi][0]), "r"(af[mi][1]), "r"(af[mi][2]), "r"(af[mi][3]),
                          "r"(bfr[ng][2]), "r"(bfr[ng][3]));
                }
        }
    }

    // ---- epilogue: dist = cnorm - 2*dot ----
    const int g = lane >> 2, t = lane & 3;
#pragma unroll
    for (int mi = 0; mi < 2; mi++) {
        int row0 = rowBase + warpM * 32 + mi * 16 + g;
#pragma unroll
        for (int ni = 0; ni < 8; ni++) {
            int col = colBase + warpN * 64 + ni * 8 + 2 * t;
            float cn0 = g_cnorm[col], cn1 = g_cnorm[col + 1];
            float2 v0 = make_float2(cn0 - 2.f * acc[mi][ni][0], cn1 - 2.f * acc[mi][ni][1]);
            float2 v1 = make_float2(cn0 - 2.f * acc[mi][ni][2], cn1 - 2.f * acc[mi][ni][3]);
            *(float2*)(g_dist + (size_t)row0 * E + col) = v0;
            *(float2*)(g_dist + (size_t)(row0 + 8) * E + col) = v1;
        }
    }
}

// ---------------- fused rescue + finalize ----------------
__global__ __launch_bounds__(256)
void epilogue_kernel(const float* __restrict__ X,
                     const float* __restrict__ C,
                     float* __restrict__ out) {
    __shared__ float q[D];                 // 16KB staging for aligned stores
    __shared__ float ws[8];
    __shared__ unsigned long long wk[8];
    __shared__ unsigned long long bestK;
    __shared__ int   cnt;
    __shared__ int   cand[64];
    __shared__ float xnorm_s;
    __shared__ int   s_idx;

    const int row = blockIdx.x;
    const int tid = threadIdx.x;
    const int lane = tid & 31, wid = tid >> 5;
    const float* drow = g_dist + (size_t)row * E;

    // ---- approx argmin over 512 entries ----
    float dval[2];
    unsigned long long k = 0xFFFFFFFFFFFFFFFFull;
#pragma unroll
    for (int i = 0; i < 2; i++) {
        int c = tid + i * 256;
        dval[i] = drow[c];
        unsigned long long kk = make_key(dval[i], c);
        k = (kk < k) ? kk : k;
    }
    for (int o = 16; o; o >>= 1) {
        unsigned long long kk = __shfl_down_sync(0xffffffffu, k, o);
        k = (kk < k) ? kk : k;
    }
    if (lane == 0) wk[wid] = k;
    if (tid == 0) cnt = 0;
    __syncthreads();
    if (tid == 0) {
        unsigned long long b = wk[0];
#pragma unroll
        for (int w = 1; w < 8; w++) if (wk[w] < b) b = wk[w];
        bestK = b;
    }
    __syncthreads();
    float bd = key_to_float(bestK);
#pragma unroll
    for (int i = 0; i < 2; i++) {
        if (dval[i] <= bd + MARGIN) {
            int p = atomicAdd(&cnt, 1);
            if (p < 64) cand[p] = tid + i * 256;
        }
    }
    __syncthreads();
    int n = cnt;
    const float4* x4 = (const float4*)(X + (size_t)row * D);

    if (n <= 1) {
        if (tid == 0) s_idx = (int)(bestK & 0xffffffffull);
        __syncthreads();
    } else {
        if (n > 64) n = 64;
        float xs = 0.f;
#pragma unroll
        for (int i = tid; i < D / 4; i += 256) {
            float4 xv = x4[i];
            xs += xv.x * xv.x + xv.y * xv.y + xv.z * xv.z + xv.w * xv.w;
        }
        for (int o = 16; o; o >>= 1) xs += __shfl_down_sync(0xffffffffu, xs, o);
        if (lane == 0) ws[wid] = xs;
        __syncthreads();
        if (tid == 0) {
            float t = 0.f;
#pragma unroll
            for (int w = 0; w < 8; w++) t += ws[w];
            xnorm_s = t;
        }
        unsigned long long bestE = 0xFFFFFFFFFFFFFFFFull;
        for (int t = 0; t < n; t++) {
            int cidx = cand[t];
            const float4* c4 = (const float4*)(C + (size_t)cidx * D);
            float s = 0.f;
#pragma unroll
            for (int i = tid; i < D / 4; i += 256) {
                float4 xv = x4[i];
                float4 cv = c4[i];
                s += xv.x * cv.x + xv.y * cv.y + xv.z * cv.z + xv.w * cv.w;
            }
            for (int o = 16; o; o >>= 1) s += __shfl_down_sync(0xffffffffu, s, o);
            __syncthreads();
            if (lane == 0) ws[wid] = s;
            __syncthreads();
            if (tid == 0) {
                float dot = 0.f;
#pragma unroll
                for (int w = 0; w < 8; w++) dot += ws[w];
                float dist = (xnorm_s + g_cnorm[cidx]) - 2.f * dot;
                unsigned long long kk = make_key(dist, cidx);
                bestE = (kk < bestE) ? kk : bestE;
            }
        }
        if (tid == 0) s_idx = (int)(bestE & 0xffffffffull);
        __syncthreads();
    }

    const int idx = s_idx;

    // ---- finalize ----
    const float4* c4 = (const float4*)(C + (size_t)idx * D);
    float s = 0.f;
#pragma unroll
    for (int i = tid; i < D / 4; i += 256) {
        float4 xv = x4[i];
        float4 cv = c4[i];
        float d0 = cv.x - xv.x, d1 = cv.y - xv.y, d2 = cv.z - xv.z, d3 = cv.w - xv.w;
        q[i * 4 + 0] = xv.x + d0;
        q[i * 4 + 1] = xv.y + d1;
        q[i * 4 + 2] = xv.z + d2;
        q[i * 4 + 3] = xv.w + d3;
        s += d0 * d0 + d1 * d1 + d2 * d2 + d3 * d3;
    }
    for (int o = 16; o; o >>= 1) s += __shfl_down_sync(0xffffffffu, s, o);
    if (lane == 0) ws[wid] = s;
    __syncthreads();
    if (tid == 0) {
        float t = 0.f;
#pragma unroll
        for (int w = 0; w < 8; w++) t += ws[w];
        atomicAdd(&g_loss, (double)t);
        atomicAdd(&g_counts[idx], 1);
    }

    // quantized_st: base offset 1 -> first aligned16 at k=3
    float* qo = out + OUT_Q_OFF + (size_t)row * D;
    if (tid == 0) { qo[0] = q[0]; qo[1] = q[1]; qo[2] = q[2]; qo[D - 1] = q[D - 1]; }
#pragma unroll
    for (int i = tid; i < 1023; i += 256) {
        int kq = 3 + i * 4;
        *(float4*)(qo + kq) = make_float4(q[kq], q[kq + 1], q[kq + 2], q[kq + 3]);
    }

    // encodings: base%4==2 -> scalars at edges, float4 middle
    float* enc = out + OUT_ENC_OFF + (size_t)row * E;
    if (tid == 0) {
        enc[0]   = (idx == 0)   ? 1.f : 0.f;
        enc[1]   = (idx == 1)   ? 1.f : 0.f;
        enc[510] = (idx == 510) ? 1.f : 0.f;
        enc[511] = (idx == 511) ? 1.f : 0.f;
    }
    for (int i = tid; i < 127; i += 256) {
        int kq = 2 + i * 4;
        float4 v = make_float4((idx == kq) ? 1.f : 0.f, (idx == kq + 1) ? 1.f : 0.f,
                               (idx == kq + 2) ? 1.f : 0.f, (idx == kq + 3) ? 1.f : 0.f);
        *(float4*)(enc + kq) = v;
    }
}

// ---------------- scalars ----------------
__global__ void scalars_kernel(float* __restrict__ out) {
    const int e = threadIdx.x;  // 512 threads
    float p = (float)g_counts[e] / (float)BROWS;
    float term = p * logf(p + 1e-10f);
    for (int o = 16; o; o >>= 1) term += __shfl_down_sync(0xffffffffu, term, o);
    __shared__ float ws[16];
    if ((e & 31) == 0) ws[e >> 5] = term;
    __syncthreads();
    if (e == 0) {
        float H = 0.f;
        for (int w = 0; w < 16; w++) H += ws[w];
        out[0] = (float)(1.25 * (g_loss / (double)NQ));
        out[OUT_PERP_OFF] = expf(-H);
    }
}

// ---------------- launch ----------------
extern "C" void kernel_launch(void* const* d_in, const int* in_sizes, int n_in,
                              void* d_out, int out_size) {
    const float* X = (const float*)d_in[0];
    const float* C = (const float*)d_in[1];
    if (n_in >= 2 && in_sizes[0] == E * D && in_sizes[1] == BROWS * D) {
        const float* t = X; X = C; C = t;
    }
    float* out = (float*)d_out;

    static bool attr_done = false;
    if (!attr_done) {
        cudaFuncSetAttribute(gemm_mma_kernel,
                             cudaFuncAttributeMaxDynamicSharedMemorySize, GEMM_SMEM);
        attr_done = true;
    }

    init_kernel<<<2, 256>>>();
    convCnorm_kernel<<<E, 128>>>(C);
    dim3 grid(E / TN, BROWS / TM);   // (2, 128) = 256 CTAs, occ 2 -> one wave
    gemm_mma_kernel<<<grid, 256, GEMM_SMEM>>>(X);
    epilogue_kernel<<<BROWS, 256>>>(X, C, out);
    scalars_kernel<<<1, E>>>(out);
}

// round 7
// speedup vs baseline: 1.0328x; 1.0328x over previous
#include <cuda_runtime.h>
#include <cuda_bf16.h>
#include <cstdint>
#include <math.h>

#define D      4096
#define E      512
#define BROWS  8192
#define NQ     (1ull*BROWS*D)
#define NENC   (1ull*BROWS*E)

#define OUT_Q_OFF    1ull
#define OUT_PERP_OFF (1ull + NQ)
#define OUT_ENC_OFF  (2ull + NQ)

#define MARGIN 4.0f

// ---------------- device scratch ----------------
__device__ float          g_cnorm[E];
__device__ float          g_dist[(size_t)BROWS * E];   // 16 MB approx distances
__device__ __nv_bfloat16  g_Cb[(size_t)E * D];         // 4 MB bf16 codebook
__device__ int            g_counts[E];
__device__ double         g_loss;

#define SWZ128(off) ((off) ^ (((off) >> 3) & 0x70))

__device__ __forceinline__ uint32_t smem_to_u32(const void* p) {
    uint32_t a;
    asm("{ .reg .u64 t; cvta.to.shared.u64 t, %1; cvt.u32.u64 %0, t; }" : "=r"(a) : "l"(p));
    return a;
}

// key packing: monotone float -> u32, argmin with ties -> lowest index
__device__ __forceinline__ unsigned long long make_key(float d, int idx) {
    unsigned int u = __float_as_uint(d);
    u = (u & 0x80000000u) ? ~u : (u | 0x80000000u);
    return ((unsigned long long)u << 32) | (unsigned int)idx;
}
__device__ __forceinline__ float key_to_float(unsigned long long k) {
    unsigned int u = (unsigned int)(k >> 32);
    u = (u & 0x80000000u) ? (u ^ 0x80000000u) : ~u;
    return __uint_as_float(u);
}

// ---------------- init ----------------
__global__ void init_kernel() {
    int i = blockIdx.x * blockDim.x + threadIdx.x;
    if (i < E)  g_counts[i] = 0;
    if (i == 0) g_loss = 0.0;
}

// ---------------- codebook: bf16 convert + exact norms (fused, 1 read) ----------------
__global__ __launch_bounds__(128)
void convCnorm_kernel(const float* __restrict__ C) {
    const int e = blockIdx.x;
    const float4* row = (const float4*)(C + (size_t)e * D);
    uint2* brow = (uint2*)(g_Cb + (size_t)e * D);
    float s = 0.f;
#pragma unroll
    for (int i = threadIdx.x; i < D / 4; i += 128) {
        float4 v = row[i];
        __nv_bfloat162 lo = __floats2bfloat162_rn(v.x, v.y);
        __nv_bfloat162 hi = __floats2bfloat162_rn(v.z, v.w);
        uint2 p; p.x = *(uint32_t*)&lo; p.y = *(uint32_t*)&hi;
        brow[i] = p;
        s += v.x * v.x + v.y * v.y + v.z * v.z + v.w * v.w;
    }
    for (int o = 16; o; o >>= 1) s += __shfl_down_sync(0xffffffffu, s, o);
    __shared__ float ws[4];
    if ((threadIdx.x & 31) == 0) ws[threadIdx.x >> 5] = s;
    __syncthreads();
    if (threadIdx.x == 0) g_cnorm[e] = ws[0] + ws[1] + ws[2] + ws[3];
}

// ---------------- mma.sync bf16 GEMM: approx distances ----------------
// CTA 512 thr = 16 warps (4M x 4N), tile M=128 x N=256, warp tile 32x64.
// K chunk = 64 bf16 (128B SW128 rows). A double-buffered (reg->STS),
// B TRIPLE-buffered cp.async with wait_group 1 (2 chunks of latency cover).
#define TM 128
#define TN 256
#define CH 64
#define NCHUNK (D / CH)          // 64
#define A_BYTES 16384            // 128 rows * 128B
#define B_BYTES 32768            // 256 rows * 128B
#define GEMM_SMEM (2*A_BYTES + 3*B_BYTES)   // 131072

__global__ __launch_bounds__(512, 1)
void gemm_mma_kernel(const float* __restrict__ X) {
    extern __shared__ __align__(1024) char smem[];
    const int tid  = threadIdx.x;
    const int lane = tid & 31;
    const int wid  = tid >> 5;
    const int warpM = wid & 3;    // 0..3 (32-row bands)
    const int warpN = wid >> 2;   // 0..3 (64-col bands)
    const int rowBase = blockIdx.y * TM;
    const int colBase = blockIdx.x * TN;

    const uint32_t sb = smem_to_u32(smem);
    uint32_t sbA[2] = { sb, sb + A_BYTES };
    uint32_t sbB[3] = { sb + 2*A_BYTES, sb + 2*A_BYTES + B_BYTES, sb + 2*A_BYTES + 2*B_BYTES };
    char* pA[2] = { smem, smem + A_BYTES };

    const float* Xg0 = X + (size_t)rowBase * D;
    const __nv_bfloat16* Cg0 = g_Cb + (size_t)colBase * D;

    // load coords: A 16 thr/row (float4), B 8 thr/row (16B)
    const int ar  = tid >> 4, ac4  = tid & 15;   // ar 0..31, rows ar+i*32
    const int br  = tid >> 3, bc16 = tid & 7;    // br 0..63, rows br+i*64

    float acc[2][8][4];
#pragma unroll
    for (int mi = 0; mi < 2; mi++)
#pragma unroll
        for (int ni = 0; ni < 8; ni++)
#pragma unroll
            for (int r = 0; r < 4; r++) acc[mi][ni][r] = 0.f;

    float4 av[4];

    // ---- preload: B chunks 0 and 1 (two committed groups), A chunk 0 in regs ----
#pragma unroll
    for (int c0 = 0; c0 < 2; c0++) {
#pragma unroll
        for (int i = 0; i < 4; i++) {
            int r = br + i * 64;
            uint32_t dst = sbB[c0] + SWZ128((uint32_t)(r * 128 + bc16 * 16));
            const __nv_bfloat16* src = Cg0 + (size_t)r * D + c0 * CH + bc16 * 8;
            asm volatile("cp.async.cg.shared.global [%0], [%1], 16;" :: "r"(dst), "l"(src));
        }
        asm volatile("cp.async.commit_group;" ::: "memory");
    }
#pragma unroll
    for (int i = 0; i < 4; i++)
        av[i] = *(const float4*)(Xg0 + (size_t)(ar + i * 32) * D + ac4 * 4);

    const int a_r = lane & 15;
    const int a_c = (lane >> 4) * 16;
    const int b_n = ((lane >> 4) << 3) + (lane & 7);
    const int b_c = ((lane >> 3) & 1) * 16;

    for (int kt = 0; kt < NCHUNK; kt++) {
        const int abuf = kt & 1;
        const int bbuf = kt % 3;

        // STS A chunk kt (convert fp32 -> bf16, SW128)
#pragma unroll
        for (int i = 0; i < 4; i++) {
            int r = ar + i * 32;
            __nv_bfloat162 lo = __floats2bfloat162_rn(av[i].x, av[i].y);
            __nv_bfloat162 hi = __floats2bfloat162_rn(av[i].z, av[i].w);
            uint2 p; p.x = *(uint32_t*)&lo; p.y = *(uint32_t*)&hi;
            *(uint2*)(pA[abuf] + SWZ128((uint32_t)(r * 128 + ac4 * 8))) = p;
        }

        // wait for B[kt]: allow one newer group (B[kt+1]) to stay in flight
        if (kt < NCHUNK - 1) {
            asm volatile("cp.async.wait_group 1;" ::: "memory");
        } else {
            asm volatile("cp.async.wait_group 0;" ::: "memory");
        }
        __syncthreads();   // B[kt] + A[kt] visible; all warps done with buffers of kt-1

        // prefetch B[kt+2] into (kt+2)%3 (now provably free) and A[kt+1] into regs
        if (kt + 2 < NCHUNK) {
            const int nb = (kt + 2) % 3;
            const int k0 = (kt + 2) * CH;
#pragma unroll
            for (int i = 0; i < 4; i++) {
                int r = br + i * 64;
                uint32_t dst = sbB[nb] + SWZ128((uint32_t)(r * 128 + bc16 * 16));
                const __nv_bfloat16* src = Cg0 + (size_t)r * D + k0 + bc16 * 8;
                asm volatile("cp.async.cg.shared.global [%0], [%1], 16;" :: "r"(dst), "l"(src));
            }
            asm volatile("cp.async.commit_group;" ::: "memory");
        }
        if (kt + 1 < NCHUNK) {
            const int k0 = (kt + 1) * CH;
#pragma unroll
            for (int i = 0; i < 4; i++)
                av[i] = *(const float4*)(Xg0 + (size_t)(ar + i * 32) * D + k0 + ac4 * 4);
        }

        // ---- compute chunk kt: 4 k16 steps ----
        const uint32_t aB = sbA[abuf], bB = sbB[bbuf];
#pragma unroll
        for (int kk = 0; kk < 4; kk++) {
            uint32_t af[2][4], bfr[4][4];
#pragma unroll
            for (int mi = 0; mi < 2; mi++) {
                uint32_t addr = aB + SWZ128((uint32_t)((warpM * 32 + mi * 16 + a_r) * 128 + kk * 32 + a_c));
                asm volatile("ldmatrix.sync.aligned.m8n8.x4.shared.b16 {%0,%1,%2,%3}, [%4];"
                    : "=r"(af[mi][0]), "=r"(af[mi][1]), "=r"(af[mi][2]), "=r"(af[mi][3]) : "r"(addr));
            }
#pragma unroll
            for (int ng = 0; ng < 4; ng++) {
                uint32_t addr = bB + SWZ128((uint32_t)((warpN * 64 + ng * 16 + b_n) * 128 + kk * 32 + b_c));
                asm volatile("ldmatrix.sync.aligned.m8n8.x4.shared.b16 {%0,%1,%2,%3}, [%4];"
                    : "=r"(bfr[ng][0]), "=r"(bfr[ng][1]), "=r"(bfr[ng][2]), "=r"(bfr[ng][3]) : "r"(addr));
            }
#pragma unroll
            for (int mi = 0; mi < 2; mi++)
#pragma unroll
                for (int ng = 0; ng < 4; ng++) {
                    asm volatile("mma.sync.aligned.m16n8k16.row.col.f32.bf16.bf16.f32 "
                        "{%0,%1,%2,%3}, {%4,%5,%6,%7}, {%8,%9}, {%0,%1,%2,%3};"
                        : "+f"(acc[mi][2*ng][0]), "+f"(acc[mi][2*ng][1]),
                          "+f"(acc[mi][2*ng][2]), "+f"(acc[mi][2*ng][3])
                        : "r"(af[mi][0]), "r"(af[mi][1]), "r"(af[mi][2]), "r"(af[mi][3]),
                          "r"(bfr[ng][0]), "r"(bfr[ng][1]));
                    asm volatile("mma.sync.aligned.m16n8k16.row.col.f32.bf16.bf16.f32 "
                        "{%0,%1,%2,%3}, {%4,%5,%6,%7}, {%8,%9}, {%0,%1,%2,%3};"
                        : "+f"(acc[mi][2*ng+1][0]), "+f"(acc[mi][2*ng+1][1]),
                          "+f"(acc[mi][2*ng+1][2]), "+f"(acc[mi][2*ng+1][3])
                        : "r"(af[mi][0]), "r"(af[mi][1]), "r"(af[mi][2]), "r"(af[mi][3]),
                          "r"(bfr[ng][2]), "r"(bfr[ng][3]));
                }
        }
    }

    // ---- epilogue: dist = cnorm - 2*dot ----
    const int g = lane >> 2, t = lane & 3;
#pragma unroll
    for (int mi = 0; mi < 2; mi++) {
        int row0 = rowBase + warpM * 32 + mi * 16 + g;
#pragma unroll
        for (int ni = 0; ni < 8; ni++) {
            int col = colBase + warpN * 64 + ni * 8 + 2 * t;
            float cn0 = g_cnorm[col], cn1 = g_cnorm[col + 1];
            float2 v0 = make_float2(cn0 - 2.f * acc[mi][ni][0], cn1 - 2.f * acc[mi][ni][1]);
            float2 v1 = make_float2(cn0 - 2.f * acc[mi][ni][2], cn1 - 2.f * acc[mi][ni][3]);
            *(float2*)(g_dist + (size_t)row0 * E + col) = v0;
            *(float2*)(g_dist + (size_t)(row0 + 8) * E + col) = v1;
        }
    }
}

// ---------------- fused rescue + finalize ----------------
__global__ __launch_bounds__(256)
void epilogue_kernel(const float* __restrict__ X,
                     const float* __restrict__ C,
                     float* __restrict__ out) {
    __shared__ float q[D];                 // 16KB staging for aligned stores
    __shared__ float ws[8];
    __shared__ unsigned long long wk[8];
    __shared__ unsigned long long bestK;
    __shared__ int   cnt;
    __shared__ int   cand[64];
    __shared__ float xnorm_s;
    __shared__ int   s_idx;

    const int row = blockIdx.x;
    const int tid = threadIdx.x;
    const int lane = tid & 31, wid = tid >> 5;
    const float* drow = g_dist + (size_t)row * E;

    // ---- approx argmin over 512 entries ----
    float dval[2];
    unsigned long long k = 0xFFFFFFFFFFFFFFFFull;
#pragma unroll
    for (int i = 0; i < 2; i++) {
        int c = tid + i * 256;
        dval[i] = drow[c];
        unsigned long long kk = make_key(dval[i], c);
        k = (kk < k) ? kk : k;
    }
    for (int o = 16; o; o >>= 1) {
        unsigned long long kk = __shfl_down_sync(0xffffffffu, k, o);
        k = (kk < k) ? kk : k;
    }
    if (lane == 0) wk[wid] = k;
    if (tid == 0) cnt = 0;
    __syncthreads();
    if (tid == 0) {
        unsigned long long b = wk[0];
#pragma unroll
        for (int w = 1; w < 8; w++) if (wk[w] < b) b = wk[w];
        bestK = b;
    }
    __syncthreads();
    float bd = key_to_float(bestK);
#pragma unroll
    for (int i = 0; i < 2; i++) {
        if (dval[i] <= bd + MARGIN) {
            int p = atomicAdd(&cnt, 1);
            if (p < 64) cand[p] = tid + i * 256;
        }
    }
    __syncthreads();
    int n = cnt;
    const float4* x4 = (const float4*)(X + (size_t)row * D);

    if (n <= 1) {
        if (tid == 0) s_idx = (int)(bestK & 0xffffffffull);
        __syncthreads();
    } else {
        if (n > 64) n = 64;
        float xs = 0.f;
#pragma unroll
        for (int i = tid; i < D / 4; i += 256) {
            float4 xv = x4[i];
            xs += xv.x * xv.x + xv.y * xv.y + xv.z * xv.z + xv.w * xv.w;
        }
        for (int o = 16; o; o >>= 1) xs += __shfl_down_sync(0xffffffffu, xs, o);
        if (lane == 0) ws[wid] = xs;
        __syncthreads();
        if (tid == 0) {
            float t = 0.f;
#pragma unroll
            for (int w = 0; w < 8; w++) t += ws[w];
            xnorm_s = t;
        }
        unsigned long long bestE = 0xFFFFFFFFFFFFFFFFull;
        for (int t = 0; t < n; t++) {
            int cidx = cand[t];
            const float4* c4 = (const float4*)(C + (size_t)cidx * D);
            float s = 0.f;
#pragma unroll
            for (int i = tid; i < D / 4; i += 256) {
                float4 xv = x4[i];
                float4 cv = c4[i];
                s += xv.x * cv.x + xv.y * cv.y + xv.z * cv.z + xv.w * cv.w;
            }
            for (int o = 16; o; o >>= 1) s += __shfl_down_sync(0xffffffffu, s, o);
            __syncthreads();
            if (lane == 0) ws[wid] = s;
            __syncthreads();
            if (tid == 0) {
                float dot = 0.f;
#pragma unroll
                for (int w = 0; w < 8; w++) dot += ws[w];
                float dist = (xnorm_s + g_cnorm[cidx]) - 2.f * dot;
                unsigned long long kk = make_key(dist, cidx);
                bestE = (kk < bestE) ? kk : bestE;
            }
        }
        if (tid == 0) s_idx = (int)(bestE & 0xffffffffull);
        __syncthreads();
    }

    const int idx = s_idx;

    // ---- finalize ----
    const float4* c4 = (const float4*)(C + (size_t)idx * D);
    float s = 0.f;
#pragma unroll
    for (int i = tid; i < D / 4; i += 256) {
        float4 xv = x4[i];
        float4 cv = c4[i];
        float d0 = cv.x - xv.x, d1 = cv.y - xv.y, d2 = cv.z - xv.z, d3 = cv.w - xv.w;
        q[i * 4 + 0] = xv.x + d0;
        q[i * 4 + 1] = xv.y + d1;
        q[i * 4 + 2] = xv.z + d2;
        q[i * 4 + 3] = xv.w + d3;
        s += d0 * d0 + d1 * d1 + d2 * d2 + d3 * d3;
    }
    for (int o = 16; o; o >>= 1) s += __shfl_down_sync(0xffffffffu, s, o);
    if (lane == 0) ws[wid] = s;
    __syncthreads();
    if (tid == 0) {
        float t = 0.f;
#pragma unroll
        for (int w = 0; w < 8; w++) t += ws[w];
        atomicAdd(&g_loss, (double)t);
        atomicAdd(&g_counts[idx], 1);
    }

    // quantized_st: base offset 1 -> first aligned16 at k=3
    float* qo = out + OUT_Q_OFF + (size_t)row * D;
    if (tid == 0) { qo[0] = q[0]; qo[1] = q[1]; qo[2] = q[2]; qo[D - 1] = q[D - 1]; }
#pragma unroll
    for (int i = tid; i < 1023; i += 256) {
        int kq = 3 + i * 4;
        *(float4*)(qo + kq) = make_float4(q[kq], q[kq + 1], q[kq + 2], q[kq + 3]);
    }

    // encodings: base%4==2 -> scalars at edges, float4 middle
    float* enc = out + OUT_ENC_OFF + (size_t)row * E;
    if (tid == 0) {
        enc[0]   = (idx == 0)   ? 1.f : 0.f;
        enc[1]   = (idx == 1)   ? 1.f : 0.f;
        enc[510] = (idx == 510) ? 1.f : 0.f;
        enc[511] = (idx == 511) ? 1.f : 0.f;
    }
    for (int i = tid; i < 127; i += 256) {
        int kq = 2 + i * 4;
        float4 v = make_float4((idx == kq) ? 1.f : 0.f, (idx == kq + 1) ? 1.f : 0.f,
                               (idx == kq + 2) ? 1.f : 0.f, (idx == kq + 3) ? 1.f : 0.f);
        *(float4*)(enc + kq) = v;
    }
}

// ---------------- scalars ----------------
__global__ void scalars_kernel(float* __restrict__ out) {
    const int e = threadIdx.x;  // 512 threads
    float p = (float)g_counts[e] / (float)BROWS;
    float term = p * logf(p + 1e-10f);
    for (int o = 16; o; o >>= 1) term += __shfl_down_sync(0xffffffffu, term, o);
    __shared__ float ws[16];
    if ((e & 31) == 0) ws[e >> 5] = term;
    __syncthreads();
    if (e == 0) {
        float H = 0.f;
        for (int w = 0; w < 16; w++) H += ws[w];
        out[0] = (float)(1.25 * (g_loss / (double)NQ));
        out[OUT_PERP_OFF] = expf(-H);
    }
}

// ---------------- launch ----------------
extern "C" void kernel_launch(void* const* d_in, const int* in_sizes, int n_in,
                              void* d_out, int out_size) {
    const float* X = (const float*)d_in[0];
    const float* C = (const float*)d_in[1];
    if (n_in >= 2 && in_sizes[0] == E * D && in_sizes[1] == BROWS * D) {
        const float* t = X; X = C; C = t;
    }
    float* out = (float*)d_out;

    static bool attr_done = false;
    if (!attr_done) {
        cudaFuncSetAttribute(gemm_mma_kernel,
                             cudaFuncAttributeMaxDynamicSharedMemorySize, GEMM_SMEM);
        attr_done = true;
    }

    init_kernel<<<2, 256>>>();
    convCnorm_kernel<<<E, 128>>>(C);
    dim3 grid(E / TN, BROWS / TM);   // (2, 64)
    gemm_mma_kernel<<<grid, 512, GEMM_SMEM>>>(X);
    epilogue_kernel<<<BROWS, 256>>>(X, C, out);
    scalars_kernel<<<1, E>>>(out);
}

// round 8
// speedup vs baseline: 1.0554x; 1.0219x over previous
#include <cuda_runtime.h>
#include <cuda_bf16.h>
#include <cstdint>
#include <math.h>

#define D      4096
#define E      512
#define BROWS  8192
#define NQ     (1ull*BROWS*D)
#define NENC   (1ull*BROWS*E)

#define OUT_Q_OFF    1ull
#define OUT_PERP_OFF (1ull + NQ)
#define OUT_ENC_OFF  (2ull + NQ)

#define MARGIN 4.0f
#define CAP    16

// ---------------- device scratch ----------------
__device__ float              g_cnorm[E];
__device__ __nv_bfloat16      g_Cb[(size_t)E * D];       // 4 MB bf16 codebook
__device__ unsigned long long g_best[BROWS];             // packed (dist,idx) min
__device__ unsigned long long g_cand[(size_t)BROWS * CAP]; // 1 MB candidate keys
__device__ int                g_ccnt[BROWS];
__device__ int                g_counts[E];
__device__ double             g_loss;

#define SWZ128(off) ((off) ^ (((off) >> 3) & 0x70))

__device__ __forceinline__ uint32_t smem_to_u32(const void* p) {
    uint32_t a;
    asm("{ .reg .u64 t; cvta.to.shared.u64 t, %1; cvt.u32.u64 %0, t; }" : "=r"(a) : "l"(p));
    return a;
}

// key packing: monotone float -> u32, argmin with ties -> lowest index
__device__ __forceinline__ unsigned long long make_key(float d, int idx) {
    unsigned int u = __float_as_uint(d);
    u = (u & 0x80000000u) ? ~u : (u | 0x80000000u);
    return ((unsigned long long)u << 32) | (unsigned int)idx;
}
__device__ __forceinline__ float key_to_float(unsigned long long k) {
    unsigned int u = (unsigned int)(k >> 32);
    u = (u & 0x80000000u) ? (u ^ 0x80000000u) : ~u;
    return __uint_as_float(u);
}

// ---------------- init ----------------
__global__ void init_kernel() {
    int i = blockIdx.x * blockDim.x + threadIdx.x;
    if (i < BROWS) { g_best[i] = 0xFFFFFFFFFFFFFFFFull; g_ccnt[i] = 0; }
    if (i < E)     g_counts[i] = 0;
    if (i == 0)    g_loss = 0.0;
}

// ---------------- codebook: bf16 convert + exact norms (fused, 1 read) ----------------
__global__ __launch_bounds__(128)
void convCnorm_kernel(const float* __restrict__ C) {
    const int e = blockIdx.x;
    const float4* row = (const float4*)(C + (size_t)e * D);
    uint2* brow = (uint2*)(g_Cb + (size_t)e * D);
    float s = 0.f;
#pragma unroll
    for (int i = threadIdx.x; i < D / 4; i += 128) {
        float4 v = row[i];
        __nv_bfloat162 lo = __floats2bfloat162_rn(v.x, v.y);
        __nv_bfloat162 hi = __floats2bfloat162_rn(v.z, v.w);
        uint2 p; p.x = *(uint32_t*)&lo; p.y = *(uint32_t*)&hi;
        brow[i] = p;
        s += v.x * v.x + v.y * v.y + v.z * v.z + v.w * v.w;
    }
    for (int o = 16; o; o >>= 1) s += __shfl_down_sync(0xffffffffu, s, o);
    __shared__ float ws[4];
    if ((threadIdx.x & 31) == 0) ws[threadIdx.x >> 5] = s;
    __syncthreads();
    if (threadIdx.x == 0) g_cnorm[e] = ws[0] + ws[1] + ws[2] + ws[3];
}

// ---------------- mma.sync bf16 GEMM + fused argmin/candidates ----------------
// R4-proven core: CTA 256 thr = 8 warps (2M x 4N), tile M=128 x N=256,
// warp tile 64x64, K chunk 64 bf16 (SW128), double-buffered smem.
#define TM 128
#define TN 256
#define CH 64
#define NCHUNK (D / CH)          // 64
#define A_BYTES 16384
#define B_BYTES 32768
#define GEMM_SMEM (2*A_BYTES + 2*B_BYTES)   // 98304

__global__ __launch_bounds__(256, 1)
void gemm_mma_kernel(const float* __restrict__ X) {
    extern __shared__ __align__(1024) char smem[];
    const int tid  = threadIdx.x;
    const int lane = tid & 31;
    const int wid  = tid >> 5;
    const int warpM = wid >> 2;   // 0..1
    const int warpN = wid & 3;    // 0..3
    const int rowBase = blockIdx.y * TM;
    const int colBase = blockIdx.x * TN;

    uint32_t sbA[2] = { smem_to_u32(smem),             smem_to_u32(smem) + A_BYTES };
    uint32_t sbB[2] = { smem_to_u32(smem) + 2*A_BYTES, smem_to_u32(smem) + 2*A_BYTES + B_BYTES };
    char* pA[2] = { smem, smem + A_BYTES };

    const float* Xg0 = X + (size_t)rowBase * D;
    const __nv_bfloat16* Cg0 = g_Cb + (size_t)colBase * D;

    const int ar  = tid >> 4, ac4  = tid & 15;   // A: rows ar+i*16
    const int br  = tid >> 3, bc16 = tid & 7;    // B: rows br+i*32

    float acc[4][8][4];
#pragma unroll
    for (int mi = 0; mi < 4; mi++)
#pragma unroll
        for (int ni = 0; ni < 8; ni++)
#pragma unroll
            for (int r = 0; r < 4; r++) acc[mi][ni][r] = 0.f;

    float4 av[8];

    // ---- preload chunk 0 ----
#pragma unroll
    for (int i = 0; i < 8; i++) {
        int r = br + i * 32;
        uint32_t dst = sbB[0] + SWZ128((uint32_t)(r * 128 + bc16 * 16));
        const __nv_bfloat16* src = Cg0 + (size_t)r * D + bc16 * 8;
        asm volatile("cp.async.cg.shared.global [%0], [%1], 16;" :: "r"(dst), "l"(src));
    }
    asm volatile("cp.async.commit_group;" ::: "memory");
#pragma unroll
    for (int i = 0; i < 8; i++)
        av[i] = *(const float4*)(Xg0 + (size_t)(ar + i * 16) * D + ac4 * 4);

    const int a_r = lane & 15;
    const int a_c = (lane >> 4) * 16;
    const int b_n = ((lane >> 4) << 3) + (lane & 7);
    const int b_c = ((lane >> 3) & 1) * 16;

    for (int kt = 0; kt < NCHUNK; kt++) {
        const int buf = kt & 1;

        // STS A (convert fp32 -> bf16, SW128)
#pragma unroll
        for (int i = 0; i < 8; i++) {
            int r = ar + i * 16;
            __nv_bfloat162 lo = __floats2bfloat162_rn(av[i].x, av[i].y);
            __nv_bfloat162 hi = __floats2bfloat162_rn(av[i].z, av[i].w);
            uint2 p; p.x = *(uint32_t*)&lo; p.y = *(uint32_t*)&hi;
            *(uint2*)(pA[buf] + SWZ128((uint32_t)(r * 128 + ac4 * 8))) = p;
        }
        asm volatile("cp.async.wait_group 0;" ::: "memory");
        __syncthreads();

        // prefetch next chunk (overlaps MMA below)
        if (kt + 1 < NCHUNK) {
            const int nb = buf ^ 1;
            const int k0 = (kt + 1) * CH;
#pragma unroll
            for (int i = 0; i < 8; i++) {
                int r = br + i * 32;
                uint32_t dst = sbB[nb] + SWZ128((uint32_t)(r * 128 + bc16 * 16));
                const __nv_bfloat16* src = Cg0 + (size_t)r * D + k0 + bc16 * 8;
                asm volatile("cp.async.cg.shared.global [%0], [%1], 16;" :: "r"(dst), "l"(src));
            }
            asm volatile("cp.async.commit_group;" ::: "memory");
#pragma unroll
            for (int i = 0; i < 8; i++)
                av[i] = *(const float4*)(Xg0 + (size_t)(ar + i * 16) * D + k0 + ac4 * 4);
        }

        // ---- compute: 4 k16 steps ----
        const uint32_t aB = sbA[buf], bB = sbB[buf];
#pragma unroll
        for (int kk = 0; kk < 4; kk++) {
            uint32_t af[4][4], bfr[4][4];
#pragma unroll
            for (int mi = 0; mi < 4; mi++) {
                uint32_t addr = aB + SWZ128((uint32_t)((warpM * 64 + mi * 16 + a_r) * 128 + kk * 32 + a_c));
                asm volatile("ldmatrix.sync.aligned.m8n8.x4.shared.b16 {%0,%1,%2,%3}, [%4];"
                    : "=r"(af[mi][0]), "=r"(af[mi][1]), "=r"(af[mi][2]), "=r"(af[mi][3]) : "r"(addr));
            }
#pragma unroll
            for (int ng = 0; ng < 4; ng++) {
                uint32_t addr = bB + SWZ128((uint32_t)((warpN * 64 + ng * 16 + b_n) * 128 + kk * 32 + b_c));
                asm volatile("ldmatrix.sync.aligned.m8n8.x4.shared.b16 {%0,%1,%2,%3}, [%4];"
                    : "=r"(bfr[ng][0]), "=r"(bfr[ng][1]), "=r"(bfr[ng][2]), "=r"(bfr[ng][3]) : "r"(addr));
            }
#pragma unroll
            for (int mi = 0; mi < 4; mi++)
#pragma unroll
                for (int ng = 0; ng < 4; ng++) {
                    asm volatile("mma.sync.aligned.m16n8k16.row.col.f32.bf16.bf16.f32 "
                        "{%0,%1,%2,%3}, {%4,%5,%6,%7}, {%8,%9}, {%0,%1,%2,%3};"
                        : "+f"(acc[mi][2*ng][0]), "+f"(acc[mi][2*ng][1]),
                          "+f"(acc[mi][2*ng][2]), "+f"(acc[mi][2*ng][3])
                        : "r"(af[mi][0]), "r"(af[mi][1]), "r"(af[mi][2]), "r"(af[mi][3]),
                          "r"(bfr[ng][0]), "r"(bfr[ng][1]));
                    asm volatile("mma.sync.aligned.m16n8k16.row.col.f32.bf16.bf16.f32 "
                        "{%0,%1,%2,%3}, {%4,%5,%6,%7}, {%8,%9}, {%0,%1,%2,%3};"
                        : "+f"(acc[mi][2*ng+1][0]), "+f"(acc[mi][2*ng+1][1]),
                          "+f"(acc[mi][2*ng+1][2]), "+f"(acc[mi][2*ng+1][3])
                        : "r"(af[mi][0]), "r"(af[mi][1]), "r"(af[mi][2]), "r"(af[mi][3]),
                          "r"(bfr[ng][2]), "r"(bfr[ng][3]));
                }
        }
    }

    // ---- fused epilogue: per-CTA row argmin + candidate push (no dist matrix) ----
    __shared__ unsigned long long rowbest[TM];
    for (int i = tid; i < TM; i += 256) rowbest[i] = 0xFFFFFFFFFFFFFFFFull;
    __syncthreads();

    const int g = lane >> 2, t = lane & 3;
    // pass 1: smem per-row min over this CTA's 256 columns
#pragma unroll
    for (int mi = 0; mi < 4; mi++) {
#pragma unroll
        for (int rr = 0; rr < 2; rr++) {
            int lrow = warpM * 64 + mi * 16 + rr * 8 + g;
            unsigned long long best = 0xFFFFFFFFFFFFFFFFull;
#pragma unroll
            for (int ni = 0; ni < 8; ni++) {
                int col = colBase + warpN * 64 + ni * 8 + 2 * t;
                float d0 = g_cnorm[col]     - 2.f * acc[mi][ni][rr * 2 + 0];
                float d1 = g_cnorm[col + 1] - 2.f * acc[mi][ni][rr * 2 + 1];
                unsigned long long k0 = make_key(d0, col);
                unsigned long long k1 = make_key(d1, col + 1);
                if (k0 < best) best = k0;
                if (k1 < best) best = k1;
            }
            atomicMin(&rowbest[lrow], best);
        }
    }
    __syncthreads();
    for (int i = tid; i < TM; i += 256)
        atomicMin(&g_best[rowBase + i], rowbest[i]);

    // pass 2: push candidates within CTA-local row min + MARGIN
#pragma unroll
    for (int mi = 0; mi < 4; mi++) {
#pragma unroll
        for (int rr = 0; rr < 2; rr++) {
            int lrow = warpM * 64 + mi * 16 + rr * 8 + g;
            int grow = rowBase + lrow;
            float thr = key_to_float(rowbest[lrow]) + MARGIN;
#pragma unroll
            for (int ni = 0; ni < 8; ni++) {
                int col = colBase + warpN * 64 + ni * 8 + 2 * t;
                float d0 = g_cnorm[col]     - 2.f * acc[mi][ni][rr * 2 + 0];
                float d1 = g_cnorm[col + 1] - 2.f * acc[mi][ni][rr * 2 + 1];
                if (d0 <= thr) {
                    int p = atomicAdd(&g_ccnt[grow], 1);
                    if (p < CAP) g_cand[(size_t)grow * CAP + p] = make_key(d0, col);
                }
                if (d1 <= thr) {
                    int p = atomicAdd(&g_ccnt[grow], 1);
                    if (p < CAP) g_cand[(size_t)grow * CAP + p] = make_key(d1, col + 1);
                }
            }
        }
    }
}

// ---------------- fused rescue + finalize ----------------
__global__ __launch_bounds__(256)
void epilogue_kernel(const float* __restrict__ X,
                     const float* __restrict__ C,
                     float* __restrict__ out) {
    __shared__ float q[D];                 // 16KB staging for aligned stores
    __shared__ float ws[8];
    __shared__ int   cand[E];
    __shared__ int   ncand;
    __shared__ float xnorm_s;
    __shared__ int   s_idx;

    const int row = blockIdx.x;
    const int tid = threadIdx.x;
    const int lane = tid & 31, wid = tid >> 5;

    const unsigned long long bk = g_best[row];
    const float gd = key_to_float(bk);
    const int gidx = (int)(bk & 0xffffffffull);
    const int cnt = g_ccnt[row];

    if (tid == 0) ncand = 0;
    __syncthreads();
    if (cnt > CAP) {
        // overflow (astronomically unlikely): exact rescue over all codes
        for (int i = tid; i < E; i += 256) cand[i] = i;
        if (tid == 0) ncand = E;
    } else {
        if (tid < cnt) {
            unsigned long long k = g_cand[(size_t)row * CAP + tid];
            if (key_to_float(k) <= gd + MARGIN) {
                int p = atomicAdd(&ncand, 1);
                cand[p] = (int)(k & 0xffffffffull);
            }
        }
    }
    __syncthreads();
    int n = ncand;
    const float4* x4 = (const float4*)(X + (size_t)row * D);

    if (n <= 1) {
        if (tid == 0) s_idx = gidx;
        __syncthreads();
    } else {
        // exact fp32 rescoring of candidates (winner is in the list)
        float xs = 0.f;
#pragma unroll
        for (int i = tid; i < D / 4; i += 256) {
            float4 xv = x4[i];
            xs += xv.x * xv.x + xv.y * xv.y + xv.z * xv.z + xv.w * xv.w;
        }
        for (int o = 16; o; o >>= 1) xs += __shfl_down_sync(0xffffffffu, xs, o);
        if (lane == 0) ws[wid] = xs;
        __syncthreads();
        if (tid == 0) {
            float t = 0.f;
#pragma unroll
            for (int w = 0; w < 8; w++) t += ws[w];
            xnorm_s = t;
        }
        unsigned long long bestE = 0xFFFFFFFFFFFFFFFFull;
        for (int t = 0; t < n; t++) {
            int cidx = cand[t];
            const float4* c4 = (const float4*)(C + (size_t)cidx * D);
            float s = 0.f;
#pragma unroll
            for (int i = tid; i < D / 4; i += 256) {
                float4 xv = x4[i];
                float4 cv = c4[i];
                s += xv.x * cv.x + xv.y * cv.y + xv.z * cv.z + xv.w * cv.w;
            }
            for (int o = 16; o; o >>= 1) s += __shfl_down_sync(0xffffffffu, s, o);
            __syncthreads();
            if (lane == 0) ws[wid] = s;
            __syncthreads();
            if (tid == 0) {
                float dot = 0.f;
#pragma unroll
                for (int w = 0; w < 8; w++) dot += ws[w];
                float dist = (xnorm_s + g_cnorm[cidx]) - 2.f * dot;
                unsigned long long kk = make_key(dist, cidx);
                bestE = (kk < bestE) ? kk : bestE;
            }
        }
        if (tid == 0) s_idx = (int)(bestE & 0xffffffffull);
        __syncthreads();
    }

    const int idx = s_idx;

    // ---- finalize ----
    const float4* c4 = (const float4*)(C + (size_t)idx * D);
    float s = 0.f;
#pragma unroll
    for (int i = tid; i < D / 4; i += 256) {
        float4 xv = x4[i];
        float4 cv = c4[i];
        float d0 = cv.x - xv.x, d1 = cv.y - xv.y, d2 = cv.z - xv.z, d3 = cv.w - xv.w;
        q[i * 4 + 0] = xv.x + d0;
        q[i * 4 + 1] = xv.y + d1;
        q[i * 4 + 2] = xv.z + d2;
        q[i * 4 + 3] = xv.w + d3;
        s += d0 * d0 + d1 * d1 + d2 * d2 + d3 * d3;
    }
    for (int o = 16; o; o >>= 1) s += __shfl_down_sync(0xffffffffu, s, o);
    if (lane == 0) ws[wid] = s;
    __syncthreads();
    if (tid == 0) {
        float t = 0.f;
#pragma unroll
        for (int w = 0; w < 8; w++) t += ws[w];
        atomicAdd(&g_loss, (double)t);
        atomicAdd(&g_counts[idx], 1);
    }

    // quantized_st: base offset 1 -> first aligned16 at k=3
    float* qo = out + OUT_Q_OFF + (size_t)row * D;
    if (tid == 0) { qo[0] = q[0]; qo[1] = q[1]; qo[2] = q[2]; qo[D - 1] = q[D - 1]; }
#pragma unroll
    for (int i = tid; i < 1023; i += 256) {
        int kq = 3 + i * 4;
        *(float4*)(qo + kq) = make_float4(q[kq], q[kq + 1], q[kq + 2], q[kq + 3]);
    }

    // encodings: base%4==2 -> scalars at edges, float4 middle
    float* enc = out + OUT_ENC_OFF + (size_t)row * E;
    if (tid == 0) {
        enc[0]   = (idx == 0)   ? 1.f : 0.f;
        enc[1]   = (idx == 1)   ? 1.f : 0.f;
        enc[510] = (idx == 510) ? 1.f : 0.f;
        enc[511] = (idx == 511) ? 1.f : 0.f;
    }
    for (int i = tid; i < 127; i += 256) {
        int kq = 2 + i * 4;
        float4 v = make_float4((idx == kq) ? 1.f : 0.f, (idx == kq + 1) ? 1.f : 0.f,
                               (idx == kq + 2) ? 1.f : 0.f, (idx == kq + 3) ? 1.f : 0.f);
        *(float4*)(enc + kq) = v;
    }
}

// ---------------- scalars ----------------
__global__ void scalars_kernel(float* __restrict__ out) {
    const int e = threadIdx.x;  // 512 threads
    float p = (float)g_counts[e] / (float)BROWS;
    float term = p * logf(p + 1e-10f);
    for (int o = 16; o; o >>= 1) term += __shfl_down_sync(0xffffffffu, term, o);
    __shared__ float ws[16];
    if ((e & 31) == 0) ws[e >> 5] = term;
    __syncthreads();
    if (e == 0) {
        float H = 0.f;
        for (int w = 0; w < 16; w++) H += ws[w];
        out[0] = (float)(1.25 * (g_loss / (double)NQ));
        out[OUT_PERP_OFF] = expf(-H);
    }
}

// ---------------- launch ----------------
extern "C" void kernel_launch(void* const* d_in, const int* in_sizes, int n_in,
                              void* d_out, int out_size) {
    const float* X = (const float*)d_in[0];
    const float* C = (const float*)d_in[1];
    if (n_in >= 2 && in_sizes[0] == E * D && in_sizes[1] == BROWS * D) {
        const float* t = X; X = C; C = t;
    }
    float* out = (float*)d_out;

    static bool attr_done = false;
    if (!attr_done) {
        cudaFuncSetAttribute(gemm_mma_kernel,
                             cudaFuncAttributeMaxDynamicSharedMemorySize, GEMM_SMEM);
        attr_done = true;
    }

    init_kernel<<<BROWS / 256, 256>>>();
    convCnorm_kernel<<<E, 128>>>(C);
    dim3 grid(E / TN, BROWS / TM);   // (2, 64)
    gemm_mma_kernel<<<grid, 256, GEMM_SMEM>>>(X);
    epilogue_kernel<<<BROWS, 256>>>(X, C, out);
    scalars_kernel<<<1, E>>>(out);
}